// round 15
// baseline (speedup 1.0000x reference)
#include <cuda_runtime.h>
#include <cuda_fp16.h>
#include <cstdint>

// Problem dims (fixed by the reference)
#define Bn 32
#define Sn 2048
#define En 1024
#define Hn 1024

// ---------------------------------------------------------------------------
// Scratch (allocation-free rule: __device__ globals)
// ---------------------------------------------------------------------------
__device__ float g_wq[Bn * Hn];      // W_q(dec_hidden)  [B,H]
__device__ float g_alpha[Bn * Sn];   // softmax(score)   [B,S]
__device__ float g_u[Bn * En];       // enc^T * alpha    [B,E]
// fp16 hi/lo splits, canonical layout (k contiguous per row)
__device__ __align__(16) __half g_ench[(size_t)Bn * Sn * En];
__device__ __align__(16) __half g_encl[(size_t)Bn * Sn * En];
__device__ __align__(16) __half g_wkh[Hn * En];   // W_k * 1024
__device__ __align__(16) __half g_wkl[Hn * En];

// ---------------------------------------------------------------------------
// Helpers
// ---------------------------------------------------------------------------
__device__ __forceinline__ uint32_t smem_u32(const void* p) {
    uint32_t a;
    asm("{ .reg .u64 t; cvta.to.shared.u64 t, %1; cvt.u32.u64 %0, t; }" : "=r"(a) : "l"(p));
    return a;
}

// m16n8k16 fp16 mma, D += A*B (row.col), fp32 accumulate. sm_80 baseline PTX.
__device__ __forceinline__ void mma_f16(float* d, const uint32_t* a,
                                        uint32_t b0, uint32_t b1) {
    asm volatile(
        "mma.sync.aligned.m16n8k16.row.col.f32.f16.f16.f32 "
        "{%0,%1,%2,%3}, {%4,%5,%6,%7}, {%8,%9}, {%0,%1,%2,%3};"
        : "+f"(d[0]), "+f"(d[1]), "+f"(d[2]), "+f"(d[3])
        : "r"(a[0]), "r"(a[1]), "r"(a[2]), "r"(a[3]), "r"(b0), "r"(b1));
}

#define LDSM_X4(r, addr)                                                        \
    asm volatile("ldmatrix.sync.aligned.m8n8.x4.shared.b16 {%0,%1,%2,%3}, [%4];" \
        : "=r"((r)[0]), "=r"((r)[1]), "=r"((r)[2]), "=r"((r)[3]) : "r"(addr))

#define CP_ASYNC16(dst, src) \
    asm volatile("cp.async.cg.shared.global [%0], [%1], 16;" \
        :: "r"(dst), "l"(src) : "memory")
#define CP_COMMIT() asm volatile("cp.async.commit_group;" ::: "memory")
#define CP_WAIT0()  asm volatile("cp.async.wait_group 0;" ::: "memory")

// Accurate fast tanh: 1 - 2/(exp(2x)+1). abs err ~2e-6, 2 MUFU.
__device__ __forceinline__ float tanh_fast(float x) {
    float e = __expf(2.0f * x);
    return 1.0f - __fdividef(2.0f, e + 1.0f);
}

// Split two floats into (hi, lo) fp16 pairs, packed as half2.
__device__ __forceinline__ void h2_split(float x, float y, uint32_t& h, uint32_t& l) {
    __half2 hh = __floats2half2_rn(x, y);
    float2 hf = __half22float2(hh);
    __half2 ll = __floats2half2_rn(x - hf.x, y - hf.y);
    h = *(uint32_t*)&hh;
    l = *(uint32_t*)&ll;
}

// Streaming global ld/st (evict-first; 268MB streams can't reuse L2 anyway)
__device__ __forceinline__ float4 ldg_cs(const float4* p) {
    float4 v;
    asm volatile("ld.global.cs.v4.f32 {%0,%1,%2,%3}, [%4];"
        : "=f"(v.x), "=f"(v.y), "=f"(v.z), "=f"(v.w) : "l"(p));
    return v;
}
__device__ __forceinline__ void stg_cs(uint4* p, uint4 v) {
    asm volatile("st.global.cs.v4.b32 [%0], {%1,%2,%3,%4};"
        :: "l"(p), "r"(v.x), "r"(v.y), "r"(v.z), "r"(v.w));
}

// ---------------------------------------------------------------------------
// Kernel 0a: enc prep — fp32 -> (hi, lo) fp16, 32 elems/thread, streaming
// ld/st hints, all loads issued up front (MLP=8).
// ---------------------------------------------------------------------------
__global__ void k_prep_enc(const float* __restrict__ src,
                           __half* __restrict__ dh, __half* __restrict__ dl,
                           int ntiles) {
    int gid = blockIdx.x * blockDim.x + threadIdx.x;
    if (gid >= ntiles) return;
    const float4* s = (const float4*)(src + (size_t)gid * 32);
    float4 f[8];
    #pragma unroll
    for (int i = 0; i < 8; i++) f[i] = ldg_cs(s + i);   // 8 independent LDG.128

    uint32_t oh[16], ol[16];
    const float* fs = &f[0].x;
    #pragma unroll
    for (int t = 0; t < 16; t++)
        h2_split(fs[2 * t], fs[2 * t + 1], oh[t], ol[t]);

    uint4* ph = (uint4*)(dh + (size_t)gid * 32);
    uint4* pl = (uint4*)(dl + (size_t)gid * 32);
    #pragma unroll
    for (int i = 0; i < 4; i++) {
        stg_cs(ph + i, make_uint4(oh[4 * i], oh[4 * i + 1], oh[4 * i + 2], oh[4 * i + 3]));
        stg_cs(pl + i, make_uint4(ol[4 * i], ol[4 * i + 1], ol[4 * i + 2], ol[4 * i + 3]));
    }
}

// ---------------------------------------------------------------------------
// Kernel 0b: Wk prep — normal stores (Wk hi/lo stay L2-hot for the GEMM).
// ---------------------------------------------------------------------------
__global__ void k_prep_wk(const float* __restrict__ src,
                          __half* __restrict__ dh, __half* __restrict__ dl,
                          int ngroups, float scale) {
    int gid = blockIdx.x * blockDim.x + threadIdx.x;
    if (gid >= ngroups) return;
    float f[16];
    const float4* s = (const float4*)(src + (size_t)gid * 16);
    *(float4*)&f[0]  = s[0];
    *(float4*)&f[4]  = s[1];
    *(float4*)&f[8]  = s[2];
    *(float4*)&f[12] = s[3];
    uint32_t oh[8], ol[8];
    #pragma unroll
    for (int t = 0; t < 8; t++)
        h2_split(f[2 * t] * scale, f[2 * t + 1] * scale, oh[t], ol[t]);
    uint4* ph = (uint4*)(dh + (size_t)gid * 16);
    uint4* pl = (uint4*)(dl + (size_t)gid * 16);
    ph[0] = make_uint4(oh[0], oh[1], oh[2], oh[3]);
    ph[1] = make_uint4(oh[4], oh[5], oh[6], oh[7]);
    pl[0] = make_uint4(ol[0], ol[1], ol[2], ol[3]);
    pl[1] = make_uint4(ol[4], ol[5], ol[6], ol[7]);
}

// ---------------------------------------------------------------------------
// Kernel 1: wq[b,h] = dec[b,:] . W_q[h,:]   + zero the score output region
// ---------------------------------------------------------------------------
__global__ void k_wq(const float* __restrict__ dec,
                     const float* __restrict__ Wq,
                     float* __restrict__ score_out) {
    __shared__ float ds[En];
    const int b  = blockIdx.y;
    const int h0 = blockIdx.x * 128;
    const int tid = threadIdx.x;

    #pragma unroll
    for (int e = tid * 4; e < En; e += 512)
        *(float4*)&ds[e] = *(const float4*)&dec[b * En + e];

    float2 z = make_float2(0.f, 0.f);
    *(float2*)&score_out[b * Sn + blockIdx.x * 256 + tid * 2] = z;

    __syncthreads();

    const int h = h0 + tid;
    const float* w = Wq + (size_t)h * En;
    float acc = 0.f;
    #pragma unroll 4
    for (int e = 0; e < En; e += 4) {
        float4 w4 = *(const float4*)&w[e];
        acc += w4.x * ds[e] + w4.y * ds[e + 1] + w4.z * ds[e + 2] + w4.w * ds[e + 3];
    }
    g_wq[b * Hn + h] = acc;
}

// ---------------------------------------------------------------------------
// Kernel 2: fp16x3 GEMM + fused tanh/V epilogue (round-13, best measured).
// ldmatrix.x4 (conflict-free 80B row pitch), 16B .cg cp.async 2-stage,
// 2 CTAs/SM, one barrier per chunk, pass-major mma.
// Tile 128(s) x 128(h) x 32(k). 256 threads = 8 warps (4m x 2n), warp 32x64.
// grid (Sn/128=16, Hn/128=8, Bn=32)
// ---------------------------------------------------------------------------
#define TM 128
#define TN 128
#define TK 32
#define ROWH 40                        // halfs per smem row (32 data + 8 pad, 80B)
#define ROWB (ROWH * 2)                // 80 bytes
#define ARR_BYTES (TM * ROWB)          // 10240 B per operand array
#define STAGE_BYTES (4 * ARR_BYTES)    // 40960 B per stage
#define NSTAGE 2
#define GEMM_SMEM (NSTAGE * STAGE_BYTES + (2 * TN + 2 * TM) * 4)   // 83456 B

__global__ void __launch_bounds__(256, 2)
k_gemm(const float* __restrict__ Vv, float* __restrict__ score) {
    extern __shared__ __half smh[];
    float* sV   = (float*)((char*)smh + NSTAGE * STAGE_BYTES);   // [128]
    float* sW   = sV + TN;                                       // [128]
    float* sred = sW + TN;                                       // [128][2]

    const int tid = threadIdx.x;
    const int wid = tid >> 5;
    const int lane = tid & 31;
    const int tig = lane & 3;          // 0..3
    const int wm  = wid >> 1;          // 0..3  (m: 32 rows each)
    const int wn  = wid & 1;           // 0..1  (n: 64 cols each)

    const int s0 = blockIdx.x * TM;
    const int h0 = blockIdx.y * TN;
    const int b  = blockIdx.z;

    // Stage V and wq tiles
    if (tid < TN) {
        sV[tid] = Vv[h0 + tid];
        sW[tid] = g_wq[b * Hn + h0 + tid];
    }

    const uint32_t smb = smem_u32(smh);

    // --- cp.async task mapping: 2 tasks/thread/array, 16B each ---
    // task = tid + 256*it -> row = task>>2 (0..127), seg = task&3 (16B units)
    size_t aOff[2], bOff[2];
    uint32_t sOff[2];
    #pragma unroll
    for (int it = 0; it < 2; it++) {
        const int task = tid + 256 * it;
        const int trow = task >> 2;
        const int tseg = task & 3;
        aOff[it] = ((size_t)(b * Sn + s0 + trow)) * En + tseg * 8;  // halfs
        bOff[it] = ((size_t)(h0 + trow)) * En + tseg * 8;
        sOff[it] = trow * ROWB + tseg * 16;                         // bytes
    }

    // --- ldmatrix lane-address bases (stage 0, ks 0) ---
    uint32_t aBase[2][2], bBase[4][2];
    {
        const int rA = lane & 15;
        const uint32_t cA = (uint32_t)(lane >> 4) << 4;   // 0 or 16 bytes
        #pragma unroll
        for (int mt = 0; mt < 2; mt++) {
            const int row = wm * 32 + mt * 16 + rA;
            aBase[mt][0] = smb + 0 * ARR_BYTES + row * ROWB + cA;
            aBase[mt][1] = smb + 1 * ARR_BYTES + row * ROWB + cA;
        }
        const int rB = ((lane >> 4) << 3) + (lane & 7);
        const uint32_t cB = (uint32_t)(lane & 8) << 1;    // 0 or 16 bytes
        #pragma unroll
        for (int q = 0; q < 4; q++) {
            const int row = wn * 64 + q * 16 + rB;
            bBase[q][0] = smb + 2 * ARR_BYTES + row * ROWB + cB;
            bBase[q][1] = smb + 3 * ARR_BYTES + row * ROWB + cB;
        }
    }

    float acc[2][8][4];
    #pragma unroll
    for (int mt = 0; mt < 2; mt++)
        #pragma unroll
        for (int nt = 0; nt < 8; nt++)
            #pragma unroll
            for (int r = 0; r < 4; r++) acc[mt][nt][r] = 0.f;

    const int NCHUNK = En / TK;   // 32

    auto issue = [&](int c, int st) {
        const uint32_t base = smb + st * STAGE_BYTES;
        const size_t ck = (size_t)c * TK;   // halfs
        #pragma unroll
        for (int it = 0; it < 2; it++) {
            CP_ASYNC16(base + sOff[it],                 (const char*)&g_ench[aOff[it] + ck]);
            CP_ASYNC16(base + ARR_BYTES + sOff[it],     (const char*)&g_encl[aOff[it] + ck]);
            CP_ASYNC16(base + 2 * ARR_BYTES + sOff[it], (const char*)&g_wkh[bOff[it] + ck]);
            CP_ASYNC16(base + 3 * ARR_BYTES + sOff[it], (const char*)&g_wkl[bOff[it] + ck]);
        }
    };

    issue(0, 0); CP_COMMIT();

    for (int c = 0; c < NCHUNK; c++) {
        const int st = c & 1;
        CP_WAIT0();
        __syncthreads();   // stage st complete+visible; all warps are past
                           // chunk c-1, so stage st^1 is free to refill
        if (c + 1 < NCHUNK) {
            issue(c + 1, st ^ 1);
            CP_COMMIT();
        }

        const uint32_t stOff = st * STAGE_BYTES;
        #pragma unroll
        for (int ks = 0; ks < 2; ks++) {
            const uint32_t off = stOff + ks * 32;     // 16 halfs
            uint32_t aH[2][4], aL[2][4];
            #pragma unroll
            for (int mt = 0; mt < 2; mt++) {
                LDSM_X4(aH[mt], aBase[mt][0] + off);
                LDSM_X4(aL[mt], aBase[mt][1] + off);
            }
            #pragma unroll
            for (int q = 0; q < 4; q++) {
                uint32_t bH[4], bL[4];
                LDSM_X4(bH, bBase[q][0] + off);
                LDSM_X4(bL, bBase[q][1] + off);
                // pass-major order: same-acc reuse distance = 3 mma
                #pragma unroll
                for (int mt = 0; mt < 2; mt++) {                     // hh
                    mma_f16(acc[mt][2 * q],     aH[mt], bH[0], bH[1]);
                    mma_f16(acc[mt][2 * q + 1], aH[mt], bH[2], bH[3]);
                }
                #pragma unroll
                for (int mt = 0; mt < 2; mt++) {                     // hl
                    mma_f16(acc[mt][2 * q],     aH[mt], bL[0], bL[1]);
                    mma_f16(acc[mt][2 * q + 1], aH[mt], bL[2], bL[3]);
                }
                #pragma unroll
                for (int mt = 0; mt < 2; mt++) {                     // lh
                    mma_f16(acc[mt][2 * q],     aL[mt], bH[0], bH[1]);
                    mma_f16(acc[mt][2 * q + 1], aL[mt], bH[2], bH[3]);
                }
            }
        }
        // no bottom barrier: top-of-next-chunk sync provides WAR safety
    }

    // ---- Epilogue: score[b, s] += sum_h V[h]*tanh(ctx/1024 + wq[h]) ----
    const int g = lane >> 2;
    const float inv_sc = 1.0f / 1024.0f;
    float p[4] = {0.f, 0.f, 0.f, 0.f};
    #pragma unroll
    for (int mt = 0; mt < 2; mt++)
        #pragma unroll
        for (int nt = 0; nt < 8; nt++) {
            const int hl = wn * 64 + nt * 8 + 2 * tig;
            const float v0 = sV[hl], v1 = sV[hl + 1];
            const float w0 = sW[hl], w1 = sW[hl + 1];
            p[mt * 2 + 0] += v0 * tanh_fast(acc[mt][nt][0] * inv_sc + w0)
                           + v1 * tanh_fast(acc[mt][nt][1] * inv_sc + w1);
            p[mt * 2 + 1] += v0 * tanh_fast(acc[mt][nt][2] * inv_sc + w0)
                           + v1 * tanh_fast(acc[mt][nt][3] * inv_sc + w1);
        }
    #pragma unroll
    for (int o = 1; o < 4; o <<= 1) {
        #pragma unroll
        for (int i = 0; i < 4; i++)
            p[i] += __shfl_xor_sync(0xFFFFFFFFu, p[i], o);
    }
    if (tig == 0) {
        #pragma unroll
        for (int mt = 0; mt < 2; mt++)
            #pragma unroll
            for (int hf = 0; hf < 2; hf++) {
                const int r = wm * 32 + mt * 16 + hf * 8 + g;
                sred[r * 2 + wn] = p[mt * 2 + hf];
            }
    }
    __syncthreads();
    if (tid < TM)
        atomicAdd(&score[b * Sn + s0 + tid], sred[tid * 2] + sred[tid * 2 + 1]);
}

// ---------------------------------------------------------------------------
// Kernel 3: per-batch softmax over S -> g_alpha; also zero g_u.
// ---------------------------------------------------------------------------
__global__ void k_softmax(const float* __restrict__ score) {
    __shared__ float sh[256];
    const int b = blockIdx.x;
    const int tid = threadIdx.x;

    float vals[8];
    float lmax = -3.4e38f;
    #pragma unroll
    for (int i = 0; i < 8; i++) {
        vals[i] = score[b * Sn + tid + i * 256];
        lmax = fmaxf(lmax, vals[i]);
    }
    sh[tid] = lmax;
    __syncthreads();
    for (int off = 128; off > 0; off >>= 1) {
        if (tid < off) sh[tid] = fmaxf(sh[tid], sh[tid + off]);
        __syncthreads();
    }
    const float m = sh[0];
    __syncthreads();

    float lsum = 0.f;
    #pragma unroll
    for (int i = 0; i < 8; i++) {
        vals[i] = __expf(vals[i] - m);
        lsum += vals[i];
    }
    sh[tid] = lsum;
    __syncthreads();
    for (int off = 128; off > 0; off >>= 1) {
        if (tid < off) sh[tid] += sh[tid + off];
        __syncthreads();
    }
    const float inv = 1.0f / sh[0];
    #pragma unroll
    for (int i = 0; i < 8; i++)
        g_alpha[b * Sn + tid + i * 256] = vals[i] * inv;

    for (int e = tid; e < En; e += 256) g_u[b * En + e] = 0.f;
}

// ---------------------------------------------------------------------------
// Kernel 4: u[b,e] = sum_s alpha[b,s] * enc[b,s,e]
// ---------------------------------------------------------------------------
__global__ void k_wenc(const float* __restrict__ enc) {
    const int b  = blockIdx.z;
    const int sc = blockIdx.y * 64;
    const int e0 = blockIdx.x * 512 + threadIdx.x * 4;

    const float* ep = enc + ((size_t)b * Sn + sc) * En + e0;
    const float* ap = g_alpha + b * Sn + sc;

    float4 acc = make_float4(0.f, 0.f, 0.f, 0.f);
    #pragma unroll 8
    for (int s = 0; s < 64; s++) {
        float a = ap[s];
        float4 v = *(const float4*)(ep + (size_t)s * En);
        acc.x += a * v.x; acc.y += a * v.y;
        acc.z += a * v.z; acc.w += a * v.w;
    }
    atomicAdd(&g_u[b * En + e0 + 0], acc.x);
    atomicAdd(&g_u[b * En + e0 + 1], acc.y);
    atomicAdd(&g_u[b * En + e0 + 2], acc.z);
    atomicAdd(&g_u[b * En + e0 + 3], acc.w);
}

// ---------------------------------------------------------------------------
// Kernel 5: hidden[b,h] = W_k[h,:] . u[b,:]
// ---------------------------------------------------------------------------
__global__ void k_hidden(const float* __restrict__ Wk, float* __restrict__ hid) {
    __shared__ float us[En];
    const int b = blockIdx.y;
    const int h = blockIdx.x * 128 + threadIdx.x;

    #pragma unroll
    for (int e = threadIdx.x * 4; e < En; e += 512)
        *(float4*)&us[e] = *(const float4*)&g_u[b * En + e];
    __syncthreads();

    const float* w = Wk + (size_t)h * En;
    float acc = 0.f;
    #pragma unroll 4
    for (int e = 0; e < En; e += 4) {
        float4 w4 = *(const float4*)&w[e];
        acc += w4.x * us[e] + w4.y * us[e + 1] + w4.z * us[e + 2] + w4.w * us[e + 3];
    }
    hid[b * Hn + h] = acc;
}

// ---------------------------------------------------------------------------
// Launch. Graph-capturable, allocation-free. Single stream (round-13 order).
// Output layout: [ hidden_state (B*H) | score (B*S) ]
// ---------------------------------------------------------------------------
extern "C" void kernel_launch(void* const* d_in, const int* in_sizes, int n_in,
                              void* d_out, int out_size) {
    const float* enc = (const float*)d_in[0];   // [B,S,E]
    const float* dec = (const float*)d_in[1];   // [B,E]
    const float* Wk  = (const float*)d_in[2];   // [H,E]
    const float* Wq  = (const float*)d_in[3];   // [H,E]
    const float* V   = (const float*)d_in[4];   // [H]

    float* out   = (float*)d_out;
    float* hid   = out;              // B*H
    float* score = out + Bn * Hn;    // B*S

    static bool attr_set = false;
    if (!attr_set) {
        cudaFuncSetAttribute(k_gemm, cudaFuncAttributeMaxDynamicSharedMemorySize,
                             GEMM_SMEM);
        attr_set = true;
    }

    void *ench, *encl, *wkh, *wkl;
    cudaGetSymbolAddress(&ench, g_ench);
    cudaGetSymbolAddress(&encl, g_encl);
    cudaGetSymbolAddress(&wkh,  g_wkh);
    cudaGetSymbolAddress(&wkl,  g_wkl);

    const int encTiles = Bn * Sn * En / 32;    // 2,097,152 (32 elems/thread)
    const int wkGroups = Hn * En / 16;         // 65,536
    k_prep_enc<<<encTiles / 256, 256>>>(enc, (__half*)ench, (__half*)encl, encTiles);
    k_prep_wk<<<wkGroups / 256, 256>>>(Wk, (__half*)wkh, (__half*)wkl, wkGroups, 1024.0f);

    k_wq<<<dim3(Hn / 128, Bn), 128>>>(dec, Wq, score);
    k_gemm<<<dim3(Sn / TM, Hn / TN, Bn), 256, GEMM_SMEM>>>(V, score);
    k_softmax<<<Bn, 256>>>(score);
    k_wenc<<<dim3(En / 512, Sn / 64, Bn), 128>>>(enc);
    k_hidden<<<dim3(Hn / 128, Bn), 128>>>(Wk, hid);
}

// round 16
// speedup vs baseline: 1.0231x; 1.0231x over previous
#include <cuda_runtime.h>
#include <cuda_fp16.h>
#include <cstdint>

// Problem dims (fixed by the reference)
#define Bn 32
#define Sn 2048
#define En 1024
#define Hn 1024

// ---------------------------------------------------------------------------
// Scratch (allocation-free rule: __device__ globals)
// ---------------------------------------------------------------------------
__device__ float g_wq[Bn * Hn];      // W_q(dec_hidden)  [B,H]
__device__ float g_alpha[Bn * Sn];   // softmax(score)   [B,S]
__device__ float g_u[Bn * En];       // enc^T * alpha    [B,E]
// fp16 hi/lo splits, canonical layout (k contiguous per row)
__device__ __align__(16) __half g_ench[(size_t)Bn * Sn * En];
__device__ __align__(16) __half g_encl[(size_t)Bn * Sn * En];
__device__ __align__(16) __half g_wkh[Hn * En];   // W_k * 1024
__device__ __align__(16) __half g_wkl[Hn * En];

// ---------------------------------------------------------------------------
// Helpers
// ---------------------------------------------------------------------------
__device__ __forceinline__ uint32_t smem_u32(const void* p) {
    uint32_t a;
    asm("{ .reg .u64 t; cvta.to.shared.u64 t, %1; cvt.u32.u64 %0, t; }" : "=r"(a) : "l"(p));
    return a;
}

// m16n8k16 fp16 mma, D += A*B (row.col), fp32 accumulate. sm_80 baseline PTX.
__device__ __forceinline__ void mma_f16(float* d, const uint32_t* a,
                                        uint32_t b0, uint32_t b1) {
    asm volatile(
        "mma.sync.aligned.m16n8k16.row.col.f32.f16.f16.f32 "
        "{%0,%1,%2,%3}, {%4,%5,%6,%7}, {%8,%9}, {%0,%1,%2,%3};"
        : "+f"(d[0]), "+f"(d[1]), "+f"(d[2]), "+f"(d[3])
        : "r"(a[0]), "r"(a[1]), "r"(a[2]), "r"(a[3]), "r"(b0), "r"(b1));
}

#define LDSM_X4(r, addr)                                                        \
    asm volatile("ldmatrix.sync.aligned.m8n8.x4.shared.b16 {%0,%1,%2,%3}, [%4];" \
        : "=r"((r)[0]), "=r"((r)[1]), "=r"((r)[2]), "=r"((r)[3]) : "r"(addr))

#define CP_ASYNC16(dst, src) \
    asm volatile("cp.async.cg.shared.global [%0], [%1], 16;" \
        :: "r"(dst), "l"(src) : "memory")
#define CP_COMMIT() asm volatile("cp.async.commit_group;" ::: "memory")
#define CP_WAIT0()  asm volatile("cp.async.wait_group 0;" ::: "memory")

// Accurate fast tanh: 1 - 2/(exp(2x)+1). abs err ~2e-6, 2 MUFU.
__device__ __forceinline__ float tanh_fast(float x) {
    float e = __expf(2.0f * x);
    return 1.0f - __fdividef(2.0f, e + 1.0f);
}

// Split two floats into (hi, lo) fp16 pairs, packed as half2.
__device__ __forceinline__ void h2_split(float x, float y, uint32_t& h, uint32_t& l) {
    __half2 hh = __floats2half2_rn(x, y);
    float2 hf = __half22float2(hh);
    __half2 ll = __floats2half2_rn(x - hf.x, y - hf.y);
    h = *(uint32_t*)&hh;
    l = *(uint32_t*)&ll;
}

// ---------------------------------------------------------------------------
// Kernel 0: fused prep — fp32 -> (hi, lo) fp16 for BOTH enc (scale 1) and
// Wk (scale 1024). One grid; groups [0, nEnc) are enc, [nEnc, nEnc+nWk) Wk.
// Per-thread body identical to the round-13 k_prep (16 elems/thread).
// ---------------------------------------------------------------------------
__global__ void k_prep2(const float* __restrict__ encSrc,
                        __half* __restrict__ encH, __half* __restrict__ encL,
                        int nEnc,
                        const float* __restrict__ wkSrc,
                        __half* __restrict__ wkH, __half* __restrict__ wkL,
                        int nTotal) {
    int gid = blockIdx.x * blockDim.x + threadIdx.x;
    if (gid >= nTotal) return;
    const float* src;
    __half *dh, *dl;
    float scale;
    size_t idx;
    if (gid < nEnc) {
        src = encSrc; dh = encH; dl = encL; scale = 1.0f; idx = (size_t)gid;
    } else {
        src = wkSrc; dh = wkH; dl = wkL; scale = 1024.0f; idx = (size_t)(gid - nEnc);
    }
    float f[16];
    const float4* s = (const float4*)(src + idx * 16);
    *(float4*)&f[0]  = s[0];
    *(float4*)&f[4]  = s[1];
    *(float4*)&f[8]  = s[2];
    *(float4*)&f[12] = s[3];
    uint32_t oh[8], ol[8];
    #pragma unroll
    for (int t = 0; t < 8; t++)
        h2_split(f[2 * t] * scale, f[2 * t + 1] * scale, oh[t], ol[t]);
    uint4* ph = (uint4*)(dh + idx * 16);
    uint4* pl = (uint4*)(dl + idx * 16);
    ph[0] = make_uint4(oh[0], oh[1], oh[2], oh[3]);
    ph[1] = make_uint4(oh[4], oh[5], oh[6], oh[7]);
    pl[0] = make_uint4(ol[0], ol[1], ol[2], ol[3]);
    pl[1] = make_uint4(ol[4], ol[5], ol[6], ol[7]);
}

// ---------------------------------------------------------------------------
// Kernel 1: wq[b,h] = dec[b,:] . W_q[h,:]   + zero the score output region
// ---------------------------------------------------------------------------
__global__ void k_wq(const float* __restrict__ dec,
                     const float* __restrict__ Wq,
                     float* __restrict__ score_out) {
    __shared__ float ds[En];
    const int b  = blockIdx.y;
    const int h0 = blockIdx.x * 128;
    const int tid = threadIdx.x;

    #pragma unroll
    for (int e = tid * 4; e < En; e += 512)
        *(float4*)&ds[e] = *(const float4*)&dec[b * En + e];

    float2 z = make_float2(0.f, 0.f);
    *(float2*)&score_out[b * Sn + blockIdx.x * 256 + tid * 2] = z;

    __syncthreads();

    const int h = h0 + tid;
    const float* w = Wq + (size_t)h * En;
    float acc = 0.f;
    #pragma unroll 4
    for (int e = 0; e < En; e += 4) {
        float4 w4 = *(const float4*)&w[e];
        acc += w4.x * ds[e] + w4.y * ds[e + 1] + w4.z * ds[e + 2] + w4.w * ds[e + 3];
    }
    g_wq[b * Hn + h] = acc;
}

// ---------------------------------------------------------------------------
// Kernel 2: fp16x3 GEMM + fused tanh/V epilogue (round-13, best measured).
// ldmatrix.x4 (conflict-free 80B row pitch), 16B .cg cp.async 2-stage,
// 2 CTAs/SM, one barrier per chunk, pass-major mma.
// Tile 128(s) x 128(h) x 32(k). 256 threads = 8 warps (4m x 2n), warp 32x64.
// grid (Sn/128=16, Hn/128=8, Bn=32)
// ---------------------------------------------------------------------------
#define TM 128
#define TN 128
#define TK 32
#define ROWH 40                        // halfs per smem row (32 data + 8 pad, 80B)
#define ROWB (ROWH * 2)                // 80 bytes
#define ARR_BYTES (TM * ROWB)          // 10240 B per operand array
#define STAGE_BYTES (4 * ARR_BYTES)    // 40960 B per stage
#define NSTAGE 2
#define GEMM_SMEM (NSTAGE * STAGE_BYTES + (2 * TN + 2 * TM) * 4)   // 83456 B

__global__ void __launch_bounds__(256, 2)
k_gemm(const float* __restrict__ Vv, float* __restrict__ score) {
    extern __shared__ __half smh[];
    float* sV   = (float*)((char*)smh + NSTAGE * STAGE_BYTES);   // [128]
    float* sW   = sV + TN;                                       // [128]
    float* sred = sW + TN;                                       // [128][2]

    const int tid = threadIdx.x;
    const int wid = tid >> 5;
    const int lane = tid & 31;
    const int tig = lane & 3;          // 0..3
    const int wm  = wid >> 1;          // 0..3  (m: 32 rows each)
    const int wn  = wid & 1;           // 0..1  (n: 64 cols each)

    const int s0 = blockIdx.x * TM;
    const int h0 = blockIdx.y * TN;
    const int b  = blockIdx.z;

    // Stage V and wq tiles
    if (tid < TN) {
        sV[tid] = Vv[h0 + tid];
        sW[tid] = g_wq[b * Hn + h0 + tid];
    }

    const uint32_t smb = smem_u32(smh);

    // --- cp.async task mapping: 2 tasks/thread/array, 16B each ---
    // task = tid + 256*it -> row = task>>2 (0..127), seg = task&3 (16B units)
    size_t aOff[2], bOff[2];
    uint32_t sOff[2];
    #pragma unroll
    for (int it = 0; it < 2; it++) {
        const int task = tid + 256 * it;
        const int trow = task >> 2;
        const int tseg = task & 3;
        aOff[it] = ((size_t)(b * Sn + s0 + trow)) * En + tseg * 8;  // halfs
        bOff[it] = ((size_t)(h0 + trow)) * En + tseg * 8;
        sOff[it] = trow * ROWB + tseg * 16;                         // bytes
    }

    // --- ldmatrix lane-address bases (stage 0, ks 0) ---
    uint32_t aBase[2][2], bBase[4][2];
    {
        const int rA = lane & 15;
        const uint32_t cA = (uint32_t)(lane >> 4) << 4;   // 0 or 16 bytes
        #pragma unroll
        for (int mt = 0; mt < 2; mt++) {
            const int row = wm * 32 + mt * 16 + rA;
            aBase[mt][0] = smb + 0 * ARR_BYTES + row * ROWB + cA;
            aBase[mt][1] = smb + 1 * ARR_BYTES + row * ROWB + cA;
        }
        const int rB = ((lane >> 4) << 3) + (lane & 7);
        const uint32_t cB = (uint32_t)(lane & 8) << 1;    // 0 or 16 bytes
        #pragma unroll
        for (int q = 0; q < 4; q++) {
            const int row = wn * 64 + q * 16 + rB;
            bBase[q][0] = smb + 2 * ARR_BYTES + row * ROWB + cB;
            bBase[q][1] = smb + 3 * ARR_BYTES + row * ROWB + cB;
        }
    }

    float acc[2][8][4];
    #pragma unroll
    for (int mt = 0; mt < 2; mt++)
        #pragma unroll
        for (int nt = 0; nt < 8; nt++)
            #pragma unroll
            for (int r = 0; r < 4; r++) acc[mt][nt][r] = 0.f;

    const int NCHUNK = En / TK;   // 32

    auto issue = [&](int c, int st) {
        const uint32_t base = smb + st * STAGE_BYTES;
        const size_t ck = (size_t)c * TK;   // halfs
        #pragma unroll
        for (int it = 0; it < 2; it++) {
            CP_ASYNC16(base + sOff[it],                 (const char*)&g_ench[aOff[it] + ck]);
            CP_ASYNC16(base + ARR_BYTES + sOff[it],     (const char*)&g_encl[aOff[it] + ck]);
            CP_ASYNC16(base + 2 * ARR_BYTES + sOff[it], (const char*)&g_wkh[bOff[it] + ck]);
            CP_ASYNC16(base + 3 * ARR_BYTES + sOff[it], (const char*)&g_wkl[bOff[it] + ck]);
        }
    };

    issue(0, 0); CP_COMMIT();

    for (int c = 0; c < NCHUNK; c++) {
        const int st = c & 1;
        CP_WAIT0();
        __syncthreads();   // stage st complete+visible; all warps are past
                           // chunk c-1, so stage st^1 is free to refill
        if (c + 1 < NCHUNK) {
            issue(c + 1, st ^ 1);
            CP_COMMIT();
        }

        const uint32_t stOff = st * STAGE_BYTES;
        #pragma unroll
        for (int ks = 0; ks < 2; ks++) {
            const uint32_t off = stOff + ks * 32;     // 16 halfs
            uint32_t aH[2][4], aL[2][4];
            #pragma unroll
            for (int mt = 0; mt < 2; mt++) {
                LDSM_X4(aH[mt], aBase[mt][0] + off);
                LDSM_X4(aL[mt], aBase[mt][1] + off);
            }
            #pragma unroll
            for (int q = 0; q < 4; q++) {
                uint32_t bH[4], bL[4];
                LDSM_X4(bH, bBase[q][0] + off);
                LDSM_X4(bL, bBase[q][1] + off);
                // pass-major order: same-acc reuse distance = 3 mma
                #pragma unroll
                for (int mt = 0; mt < 2; mt++) {                     // hh
                    mma_f16(acc[mt][2 * q],     aH[mt], bH[0], bH[1]);
                    mma_f16(acc[mt][2 * q + 1], aH[mt], bH[2], bH[3]);
                }
                #pragma unroll
                for (int mt = 0; mt < 2; mt++) {                     // hl
                    mma_f16(acc[mt][2 * q],     aH[mt], bL[0], bL[1]);
                    mma_f16(acc[mt][2 * q + 1], aH[mt], bL[2], bL[3]);
                }
                #pragma unroll
                for (int mt = 0; mt < 2; mt++) {                     // lh
                    mma_f16(acc[mt][2 * q],     aL[mt], bH[0], bH[1]);
                    mma_f16(acc[mt][2 * q + 1], aL[mt], bH[2], bH[3]);
                }
            }
        }
        // no bottom barrier: top-of-next-chunk sync provides WAR safety
    }

    // ---- Epilogue: score[b, s] += sum_h V[h]*tanh(ctx/1024 + wq[h]) ----
    const int g = lane >> 2;
    const float inv_sc = 1.0f / 1024.0f;
    float p[4] = {0.f, 0.f, 0.f, 0.f};
    #pragma unroll
    for (int mt = 0; mt < 2; mt++)
        #pragma unroll
        for (int nt = 0; nt < 8; nt++) {
            const int hl = wn * 64 + nt * 8 + 2 * tig;
            const float v0 = sV[hl], v1 = sV[hl + 1];
            const float w0 = sW[hl], w1 = sW[hl + 1];
            p[mt * 2 + 0] += v0 * tanh_fast(acc[mt][nt][0] * inv_sc + w0)
                           + v1 * tanh_fast(acc[mt][nt][1] * inv_sc + w1);
            p[mt * 2 + 1] += v0 * tanh_fast(acc[mt][nt][2] * inv_sc + w0)
                           + v1 * tanh_fast(acc[mt][nt][3] * inv_sc + w1);
        }
    #pragma unroll
    for (int o = 1; o < 4; o <<= 1) {
        #pragma unroll
        for (int i = 0; i < 4; i++)
            p[i] += __shfl_xor_sync(0xFFFFFFFFu, p[i], o);
    }
    if (tig == 0) {
        #pragma unroll
        for (int mt = 0; mt < 2; mt++)
            #pragma unroll
            for (int hf = 0; hf < 2; hf++) {
                const int r = wm * 32 + mt * 16 + hf * 8 + g;
                sred[r * 2 + wn] = p[mt * 2 + hf];
            }
    }
    __syncthreads();
    if (tid < TM)
        atomicAdd(&score[b * Sn + s0 + tid], sred[tid * 2] + sred[tid * 2 + 1]);
}

// ---------------------------------------------------------------------------
// Kernel 3: per-batch softmax over S -> g_alpha; also zero g_u.
// ---------------------------------------------------------------------------
__global__ void k_softmax(const float* __restrict__ score) {
    __shared__ float sh[256];
    const int b = blockIdx.x;
    const int tid = threadIdx.x;

    float vals[8];
    float lmax = -3.4e38f;
    #pragma unroll
    for (int i = 0; i < 8; i++) {
        vals[i] = score[b * Sn + tid + i * 256];
        lmax = fmaxf(lmax, vals[i]);
    }
    sh[tid] = lmax;
    __syncthreads();
    for (int off = 128; off > 0; off >>= 1) {
        if (tid < off) sh[tid] = fmaxf(sh[tid], sh[tid + off]);
        __syncthreads();
    }
    const float m = sh[0];
    __syncthreads();

    float lsum = 0.f;
    #pragma unroll
    for (int i = 0; i < 8; i++) {
        vals[i] = __expf(vals[i] - m);
        lsum += vals[i];
    }
    sh[tid] = lsum;
    __syncthreads();
    for (int off = 128; off > 0; off >>= 1) {
        if (tid < off) sh[tid] += sh[tid + off];
        __syncthreads();
    }
    const float inv = 1.0f / sh[0];
    #pragma unroll
    for (int i = 0; i < 8; i++)
        g_alpha[b * Sn + tid + i * 256] = vals[i] * inv;

    for (int e = tid; e < En; e += 256) g_u[b * En + e] = 0.f;
}

// ---------------------------------------------------------------------------
// Kernel 4: u[b,e] = sum_s alpha[b,s] * enc[b,s,e]
// ---------------------------------------------------------------------------
__global__ void k_wenc(const float* __restrict__ enc) {
    const int b  = blockIdx.z;
    const int sc = blockIdx.y * 64;
    const int e0 = blockIdx.x * 512 + threadIdx.x * 4;

    const float* ep = enc + ((size_t)b * Sn + sc) * En + e0;
    const float* ap = g_alpha + b * Sn + sc;

    float4 acc = make_float4(0.f, 0.f, 0.f, 0.f);
    #pragma unroll 4
    for (int s = 0; s < 64; s++) {
        float a = ap[s];
        float4 v = *(const float4*)(ep + (size_t)s * En);
        acc.x += a * v.x; acc.y += a * v.y;
        acc.z += a * v.z; acc.w += a * v.w;
    }
    atomicAdd(&g_u[b * En + e0 + 0], acc.x);
    atomicAdd(&g_u[b * En + e0 + 1], acc.y);
    atomicAdd(&g_u[b * En + e0 + 2], acc.z);
    atomicAdd(&g_u[b * En + e0 + 3], acc.w);
}

// ---------------------------------------------------------------------------
// Kernel 5: hidden[b,h] = W_k[h,:] . u[b,:]
// ---------------------------------------------------------------------------
__global__ void k_hidden(const float* __restrict__ Wk, float* __restrict__ hid) {
    __shared__ float us[En];
    const int b = blockIdx.y;
    const int h = blockIdx.x * 128 + threadIdx.x;

    #pragma unroll
    for (int e = threadIdx.x * 4; e < En; e += 512)
        *(float4*)&us[e] = *(const float4*)&g_u[b * En + e];
    __syncthreads();

    const float* w = Wk + (size_t)h * En;
    float acc = 0.f;
    #pragma unroll 4
    for (int e = 0; e < En; e += 4) {
        float4 w4 = *(const float4*)&w[e];
        acc += w4.x * us[e] + w4.y * us[e + 1] + w4.z * us[e + 2] + w4.w * us[e + 3];
    }
    hid[b * Hn + h] = acc;
}

// ---------------------------------------------------------------------------
// Launch. Graph-capturable, allocation-free. Single stream (round-13 order,
// with the two prep launches fused into one grid).
// Output layout: [ hidden_state (B*H) | score (B*S) ]
// ---------------------------------------------------------------------------
extern "C" void kernel_launch(void* const* d_in, const int* in_sizes, int n_in,
                              void* d_out, int out_size) {
    const float* enc = (const float*)d_in[0];   // [B,S,E]
    const float* dec = (const float*)d_in[1];   // [B,E]
    const float* Wk  = (const float*)d_in[2];   // [H,E]
    const float* Wq  = (const float*)d_in[3];   // [H,E]
    const float* V   = (const float*)d_in[4];   // [H]

    float* out   = (float*)d_out;
    float* hid   = out;              // B*H
    float* score = out + Bn * Hn;    // B*S

    static bool attr_set = false;
    if (!attr_set) {
        cudaFuncSetAttribute(k_gemm, cudaFuncAttributeMaxDynamicSharedMemorySize,
                             GEMM_SMEM);
        attr_set = true;
    }

    void *ench, *encl, *wkh, *wkl;
    cudaGetSymbolAddress(&ench, g_ench);
    cudaGetSymbolAddress(&encl, g_encl);
    cudaGetSymbolAddress(&wkh,  g_wkh);
    cudaGetSymbolAddress(&wkl,  g_wkl);

    const int encGroups = Bn * Sn * En / 16;   // 4,194,304
    const int wkGroups  = Hn * En / 16;        // 65,536
    const int totGroups = encGroups + wkGroups;
    k_prep2<<<(totGroups + 255) / 256, 256>>>(
        enc, (__half*)ench, (__half*)encl, encGroups,
        Wk, (__half*)wkh, (__half*)wkl, totGroups);

    k_wq<<<dim3(Hn / 128, Bn), 128>>>(dec, Wq, score);
    k_gemm<<<dim3(Sn / TM, Hn / TN, Bn), 256, GEMM_SMEM>>>(V, score);
    k_softmax<<<Bn, 256>>>(score);
    k_wenc<<<dim3(En / 512, Sn / 64, Bn), 128>>>(enc);
    k_hidden<<<dim3(Hn / 128, Bn), 128>>>(Wk, hid);
}